// round 5
// baseline (speedup 1.0000x reference)
#include <cuda_runtime.h>
#include <cstdint>

// KV-cache concat: out = [keys | values]
//   keys   = concat(key_cache[B,H,S,D],   key_states[B,H,1,D],   dim=-2)
//   values = concat(value_cache[B,H,S,D], value_states[B,H,1,D], dim=-2)
// B=8, H=32, S=4096, D=128, f32. Pure HBM-bound streaming copy.
//
// R5: revert to UNROLL=8 (R4's 16 was neutral), and make each warp's 8
// front-batched float4 loads cover one CONTIGUOUS 4KB chunk (u-stride = 32
// float4 instead of 256) for DRAM row-buffer locality in the in-flight
// window. Stores likewise form contiguous 4KB runs per warp. Everything
// else as R3: branch-free mapping (out = j + (j>>17)*32), streaming hints,
// fused state append in the first 32 blocks per tensor, exact grid.

static constexpr int B = 8;
static constexpr int H = 32;
static constexpr int S = 4096;
static constexpr int D = 128;
static constexpr int D4 = D / 4;                        // 32 float4 per row
static constexpr int SLAB4 = (S + 1) * D4;              // 131104 float4 per (b,h)
static constexpr long long CACHE4 = (long long)B * H * S * D4;   // 2^25
static constexpr long long TENSOR4 = (long long)B * H * SLAB4;   // float4 per out tensor

static constexpr int TPB = 256;
static constexpr int UNROLL = 8;
static constexpr int BLOCKS_PER_TENSOR = (int)(CACHE4 / (TPB * UNROLL));  // 16384 exact
static constexpr int STATE4_PER_TENSOR = B * H * D4;    // 8192 float4
static constexpr int STATE_BLOCKS = STATE4_PER_TENSOR / TPB;  // 32

__global__ __launch_bounds__(TPB)
void kv_concat_fused_kernel(const float4* __restrict__ key_cache,
                            const float4* __restrict__ value_cache,
                            const float4* __restrict__ key_states,
                            const float4* __restrict__ value_states,
                            float4* __restrict__ out)
{
    const int t = blockIdx.y;                       // 0 = keys, 1 = values
    const float4* __restrict__ src = t ? value_cache : key_cache;
    float4* __restrict__ dst = out + (long long)t * TENSOR4;

    const int warp = threadIdx.x >> 5;
    const int lane = threadIdx.x & 31;

    // Each warp owns a contiguous UNROLL*32 float4 (4KB) chunk of the block's
    // TPB*UNROLL range; unroll steps walk consecutive 512B slices of it.
    const long long j0 = (long long)blockIdx.x * (TPB * UNROLL)
                       + (long long)warp * (UNROLL * 32) + lane;

    // Front-batched loads (MLP = 8), streaming (evict-first) reads.
    float4 v[UNROLL];
#pragma unroll
    for (int u = 0; u < UNROLL; u++)
        v[u] = __ldcs(src + (j0 + u * 32));

    // Streaming stores. out index = j + (bh<<5), bh = j>>17 (S*D4 = 2^17).
#pragma unroll
    for (int u = 0; u < UNROLL; u++) {
        long long j = j0 + u * 32;
        __stcs(dst + (j + ((j >> 17) << 5)), v[u]);
    }

    // Fused state append: first STATE_BLOCKS blocks of each tensor write the
    // single new row per (b,h). One extra float4 per thread here (2 MB total).
    if (blockIdx.x < STATE_BLOCKS) {
        const int i = blockIdx.x * TPB + threadIdx.x;   // 0..8191
        const int bh = i >> 5;                          // 0..255
        const int ln = i & 31;                          // 0..31
        const float4* __restrict__ states = t ? value_states : key_states;
        float4 sv = __ldcs(states + ((long long)bh * D4 + ln));
        dst[(long long)bh * SLAB4 + (long long)S * D4 + ln] = sv;
    }
}

extern "C" void kernel_launch(void* const* d_in, const int* in_sizes, int n_in,
                              void* d_out, int out_size)
{
    const float4* key_cache    = (const float4*)d_in[0];
    const float4* value_cache  = (const float4*)d_in[1];
    const float4* key_states   = (const float4*)d_in[2];
    const float4* value_states = (const float4*)d_in[3];
    float4* out = (float4*)d_out;

    dim3 grid(BLOCKS_PER_TENSOR, 2, 1);             // (16384, 2)
    kv_concat_fused_kernel<<<grid, TPB>>>(key_cache, value_cache,
                                          key_states, value_states, out);
}

// round 6
// speedup vs baseline: 1.0071x; 1.0071x over previous
#include <cuda_runtime.h>
#include <cstdint>

// KV-cache concat: out = [keys | values]
//   keys   = concat(key_cache[B,H,S,D],   key_states[B,H,1,D],   dim=-2)
//   values = concat(value_cache[B,H,S,D], value_states[B,H,1,D], dim=-2)
// B=8, H=32, S=4096, D=128, f32. Pure HBM-bound streaming copy.
//
// R6: best-known configuration (== R3: UNROLL=8, u-stride=TPB strided
// interleave, streaming hints, fused state append, exact grid) with 32-bit
// index arithmetic (all per-tensor indices < 2^31). R4 (UNROLL=16) and R5
// (per-warp contiguous chunks) were both measured regressions; the strided
// MLP=8 window at 88.4% DRAM is the empirical floor for this bidirectional
// stream (B300 HBM uniformity band: 88-92%).

static constexpr int B = 8;
static constexpr int H = 32;
static constexpr int S = 4096;
static constexpr int D = 128;
static constexpr int D4 = D / 4;                        // 32 float4 per row
static constexpr int SLAB4 = (S + 1) * D4;              // 131104 float4 per (b,h)
static constexpr unsigned CACHE4 = (unsigned)B * H * S * D4;     // 2^25
static constexpr long long TENSOR4 = (long long)B * H * SLAB4;   // float4 per out tensor

static constexpr int TPB = 256;
static constexpr int UNROLL = 8;
static constexpr int BLOCKS_PER_TENSOR = (int)(CACHE4 / (TPB * UNROLL));  // 16384 exact
static constexpr int STATE_BLOCKS = (B * H * D4) / TPB; // 32

__global__ __launch_bounds__(TPB)
void kv_concat_fused_kernel(const float4* __restrict__ key_cache,
                            const float4* __restrict__ value_cache,
                            const float4* __restrict__ key_states,
                            const float4* __restrict__ value_states,
                            float4* __restrict__ out)
{
    const int t = blockIdx.y;                       // 0 = keys, 1 = values
    const float4* __restrict__ src = t ? value_cache : key_cache;
    float4* __restrict__ dst = out + (long long)t * TENSOR4;

    const unsigned j0 = blockIdx.x * (TPB * UNROLL) + threadIdx.x;

    // Front-batched loads (MLP = 8), streaming (evict-first) reads.
    // u-stride = TPB: the warp's in-flight window interleaves across the
    // block's 32KB range (best measured channel/slice spread).
    float4 v[UNROLL];
#pragma unroll
    for (int u = 0; u < UNROLL; u++)
        v[u] = __ldcs(src + (j0 + u * TPB));

    // Streaming stores. out index = j + (bh<<5), bh = j>>17 (S*D4 = 2^17).
    // Max index = TENSOR4-1 < 2^31, so unsigned 32-bit is exact.
#pragma unroll
    for (int u = 0; u < UNROLL; u++) {
        unsigned j = j0 + u * TPB;
        __stcs(dst + (j + ((j >> 17) << 5)), v[u]);
    }

    // Fused state append: first STATE_BLOCKS blocks of each tensor write the
    // single new row per (b,h). One extra float4 per thread here (2 MB total).
    if (blockIdx.x < STATE_BLOCKS) {
        const unsigned i = blockIdx.x * TPB + threadIdx.x;  // 0..8191
        const unsigned bh = i >> 5;                         // 0..255
        const unsigned ln = i & 31;                         // 0..31
        const float4* __restrict__ states = t ? value_states : key_states;
        float4 sv = __ldcs(states + (bh * (unsigned)D4 + ln));
        dst[bh * (unsigned)SLAB4 + (unsigned)(S * D4) + ln] = sv;
    }
}

extern "C" void kernel_launch(void* const* d_in, const int* in_sizes, int n_in,
                              void* d_out, int out_size)
{
    const float4* key_cache    = (const float4*)d_in[0];
    const float4* value_cache  = (const float4*)d_in[1];
    const float4* key_states   = (const float4*)d_in[2];
    const float4* value_states = (const float4*)d_in[3];
    float4* out = (float4*)d_out;

    dim3 grid(BLOCKS_PER_TENSOR, 2, 1);             // (16384, 2)
    kv_concat_fused_kernel<<<grid, TPB>>>(key_cache, value_cache,
                                          key_states, value_states, out);
}